// round 12
// baseline (speedup 1.0000x reference)
#include <cuda_runtime.h>
#include <math.h>

// ---------------------------------------------------------------------------
// SwitchMoE, shapes fixed by the problem:
//   B=8, T=2048, D=1024, F=4096, E=16  -> tokens=16384
//   capacity = int(1.25*tokens/E) = 1280,  K = (tokens-1)//capacity + 1 = 13
//
// Key reductions vs the dense reference:
//  * only tokens with per-expert rank % 1280 == 0 are processed (~1/expert)
//  * nonzero(size=K, fill_value=0) artifact: for e0 = top1[token 0], the
//    K - kept_e0 fill slots are VALID (keep[0,e0]==True) and all point at
//    token 0 -> token 0's expert output is scaled by (K - kept_e0 + 1).
//  * valid kept tokens are unique across experts -> plain stores into a
//    zeroed output (zeroing fused into the router kernel).
// ---------------------------------------------------------------------------

#define TOKENS 16384
#define DD     1024
#define EE     16
#define FF     4096
#define CAP    1280
#define KK     13
#define NW     (EE * KK)   /* 208 */

// ---- device scratch (no allocations allowed) ------------------------------
__device__ int   g_top1[TOKENS];
__device__ float g_top1p[TOKENS];
__device__ float g_psum[EE];
__device__ int   g_wtok[NW];
__device__ float g_wscale[NW];
__device__ float g_h[(size_t)NW * FF];   // ~3.4 MB

// ---------------------------------------------------------------------------
__global__ void moe_init_kernel() {
    if (threadIdx.x < EE) g_psum[threadIdx.x] = 0.0f;
}

// ---------------------------------------------------------------------------
// Router: 16 tokens / block (8 warps x 2 tokens). Wr staged in shared in two
// 8-expert passes (32KB); x rows held in registers (2 x 8 float4 per lane)
// so each LDS.128 of Wr feeds 8 FMAs. Also zeroes the output rows.
// ---------------------------------------------------------------------------
__global__ void __launch_bounds__(256)
router_kernel(const float* __restrict__ x,
              const float* __restrict__ Wr,
              float* __restrict__ out) {
    __shared__ float sWr[8 * DD];   // 32 KB
    __shared__ float sP[EE];

    const int tid  = threadIdx.x;
    const int warp = tid >> 5;
    const int lane = tid & 31;
    const int tBase = blockIdx.x * 16;
    const int t0 = tBase + warp * 2;

    // zero the 16 output rows this block owns
    {
        float4* o = (float4*)(out + (size_t)tBase * DD);
        const float4 z = make_float4(0.f, 0.f, 0.f, 0.f);
        #pragma unroll
        for (int j = tid; j < 16 * DD / 4; j += 256) o[j] = z;
    }
    if (tid < EE) sP[tid] = 0.0f;

    // x rows for the warp's two tokens -> registers
    float4 xa[8], xb[8];
    {
        const float4* X0 = (const float4*)(x + (size_t)t0 * DD);
        const float4* X1 = (const float4*)(x + (size_t)(t0 + 1) * DD);
        #pragma unroll
        for (int i = 0; i < 8; i++) { xa[i] = X0[lane + i * 32]; xb[i] = X1[lane + i * 32]; }
    }

    float acc0[EE], acc1[EE];
    #pragma unroll
    for (int e = 0; e < EE; e++) { acc0[e] = 0.f; acc1[e] = 0.f; }

    #pragma unroll
    for (int pass = 0; pass < 2; pass++) {
        __syncthreads();
        {
            const float4* wsrc = (const float4*)(Wr + (size_t)pass * 8 * DD);
            float4* sdst = (float4*)sWr;
            #pragma unroll
            for (int j = tid; j < 8 * DD / 4; j += 256) sdst[j] = wsrc[j];
        }
        __syncthreads();
        #pragma unroll
        for (int e8 = 0; e8 < 8; e8++) {
            const float4* w = (const float4*)(sWr + e8 * DD);
            float s0 = 0.f, s1 = 0.f;
            #pragma unroll
            for (int i = 0; i < 8; i++) {
                float4 wv = w[lane + i * 32];
                s0 += xa[i].x * wv.x + xa[i].y * wv.y + xa[i].z * wv.z + xa[i].w * wv.w;
                s1 += xb[i].x * wv.x + xb[i].y * wv.y + xb[i].z * wv.z + xb[i].w * wv.w;
            }
            acc0[pass * 8 + e8] += s0;
            acc1[pass * 8 + e8] += s1;
        }
    }

    // reduce all 32 partial logits across the warp
    #pragma unroll
    for (int off = 16; off; off >>= 1) {
        #pragma unroll
        for (int e = 0; e < EE; e++) {
            acc0[e] += __shfl_xor_sync(0xffffffffu, acc0[e], off);
            acc1[e] += __shfl_xor_sync(0xffffffffu, acc1[e], off);
        }
    }

    if (lane < 2) {
        const float* a = lane ? acc1 : acc0;
        const int t = t0 + lane;
        float m = a[0]; int am = 0;
        #pragma unroll
        for (int e = 1; e < EE; e++) if (a[e] > m) { m = a[e]; am = e; }
        float p[EE];
        float s = 0.f;
        #pragma unroll
        for (int e = 0; e < EE; e++) { p[e] = expf(a[e] - m); s += p[e]; }
        const float inv = 1.0f / s;
        g_top1[t]  = am;
        g_top1p[t] = p[am] * inv;
        #pragma unroll
        for (int e = 0; e < EE; e++) atomicAdd(&sP[e], p[e] * inv);
    }
    __syncthreads();
    if (tid < EE) atomicAdd(&g_psum[tid], sP[tid]);
}

// ---------------------------------------------------------------------------
// Scan: 1 block, 16 warps; warp e walks tokens in order via ballot to get
// exact in-order ranks, records tokens with rank % CAP == 0, applies the
// token-0 fill multiplier, and writes lb_loss.
// ---------------------------------------------------------------------------
__global__ void __launch_bounds__(512)
scan_kernel(float* __restrict__ out, int out_size) {
    const int tid  = threadIdx.x;
    const int e    = tid >> 5;
    const int lane = tid & 31;
    __shared__ int sCnt[EE];

    if (lane < KK) { g_wtok[e * KK + lane] = -1; g_wscale[e * KK + lane] = 0.f; }

    int cnt = 0;
    #pragma unroll 8
    for (int base = 0; base < TOKENS; base += 32) {
        const int t = base + lane;
        const bool m = (g_top1[t] == e);
        const unsigned msk = __ballot_sync(0xffffffffu, m);
        if (m) {
            const int r = cnt + __popc(msk & ((1u << lane) - 1u));
            if (r % CAP == 0) {
                const int slot = r / CAP;   // < KK by construction
                g_wtok[e * KK + slot]   = t;
                g_wscale[e * KK + slot] = g_top1p[t];
            }
        }
        cnt += __popc(msk);
    }
    if (lane == 0) sCnt[e] = cnt;
    __syncthreads();

    if (tid == 0) {
        // nonzero(..., size=K, fill_value=0) artifact: token 0's expert
        // contributes (K - kept + 1) times at token 0.
        const int e0 = g_top1[0];
        const int c0 = sCnt[e0];               // >= 1 always
        const int kept0 = (c0 - 1) / CAP + 1;  // in [1, K]
        g_wscale[e0 * KK + 0] *= (float)(KK - kept0 + 1);

        if (out_size > TOKENS * DD) {
            float lb = 0.f;
            for (int j = 0; j < EE; j++)
                lb += ((float)sCnt[j] / (float)TOKENS) * (g_psum[j] / (float)TOKENS);
            out[(size_t)TOKENS * DD] = lb * (float)EE * 0.01f;
        }
    }
}

// ---------------------------------------------------------------------------
// FFN1: h = gelu(W1[e] @ x[t] + b1[e]), exact erf gelu.
// grid(F/8, E): block = 8 warps, warp per f-row, loops over kept slots of e.
// ---------------------------------------------------------------------------
__global__ void __launch_bounds__(256)
ffn1_kernel(const float* __restrict__ x,
            const float* __restrict__ W1,
            const float* __restrict__ b1) {
    __shared__ float sx[DD];   // 4 KB
    const int tid  = threadIdx.x;
    const int warp = tid >> 5;
    const int lane = tid & 31;
    const int e    = blockIdx.y;
    const int f    = blockIdx.x * 8 + warp;

    for (int k = 0; k < KK; k++) {
        const int t = g_wtok[e * KK + k];
        if (t < 0) break;             // slots filled contiguously
        __syncthreads();
        {
            const float4* xs = (const float4*)(x + (size_t)t * DD);
            ((float4*)sx)[tid] = xs[tid];   // 256 threads == D/4
        }
        __syncthreads();

        const float4* wrow = (const float4*)(W1 + ((size_t)e * FF + f) * DD);
        const float4* xv   = (const float4*)sx;
        float s = 0.f;
        #pragma unroll
        for (int i = 0; i < 8; i++) {
            const float4 wv = wrow[lane + i * 32];
            const float4 xx = xv[lane + i * 32];
            s += wv.x * xx.x + wv.y * xx.y + wv.z * xx.z + wv.w * xx.w;
        }
        #pragma unroll
        for (int off = 16; off; off >>= 1) s += __shfl_xor_sync(0xffffffffu, s, off);
        if (lane == 0) {
            const float v = s + b1[e * FF + f];
            const float g = 0.5f * v * (1.0f + erff(v * 0.70710678118654752f));
            g_h[((size_t)(e * KK + k)) * FF + f] = g;
        }
    }
}

// ---------------------------------------------------------------------------
// FFN2: out[t] = (W2[e] @ h + b2[e]) * scale. Kept tokens are unique across
// experts -> plain store into the zeroed output. grid(D/8, E).
// ---------------------------------------------------------------------------
__global__ void __launch_bounds__(256)
ffn2_kernel(const float* __restrict__ W2,
            const float* __restrict__ b2,
            float* __restrict__ out) {
    __shared__ float sh[FF];   // 16 KB
    const int tid  = threadIdx.x;
    const int warp = tid >> 5;
    const int lane = tid & 31;
    const int e    = blockIdx.y;
    const int d    = blockIdx.x * 8 + warp;

    for (int k = 0; k < KK; k++) {
        const int t = g_wtok[e * KK + k];
        if (t < 0) break;
        const float scale = g_wscale[e * KK + k];
        __syncthreads();
        {
            const float4* hs = (const float4*)(g_h + ((size_t)(e * KK + k)) * FF);
            float4* sd = (float4*)sh;
            #pragma unroll
            for (int j = tid; j < FF / 4; j += 256) sd[j] = hs[j];
        }
        __syncthreads();

        const float4* wrow = (const float4*)(W2 + ((size_t)e * DD + d) * FF);
        const float4* hv   = (const float4*)sh;
        float s = 0.f;
        #pragma unroll 8
        for (int i = 0; i < 32; i++) {
            const float4 wv = wrow[lane + i * 32];
            const float4 hh = hv[lane + i * 32];
            s += wv.x * hh.x + wv.y * hh.y + wv.z * hh.z + wv.w * hh.w;
        }
        #pragma unroll
        for (int off = 16; off; off >>= 1) s += __shfl_xor_sync(0xffffffffu, s, off);
        if (lane == 0)
            out[(size_t)t * DD + d] = (s + b2[e * DD + d]) * scale;
    }
}

// ---------------------------------------------------------------------------
extern "C" void kernel_launch(void* const* d_in, const int* in_sizes, int n_in,
                              void* d_out, int out_size) {
    const float* x  = (const float*)d_in[0];
    const float* Wr = (const float*)d_in[1];
    const float* W1 = (const float*)d_in[2];
    const float* b1 = (const float*)d_in[3];
    const float* W2 = (const float*)d_in[4];
    const float* b2 = (const float*)d_in[5];
    float* out = (float*)d_out;
    (void)in_sizes; (void)n_in;

    // zero anything beyond the main tensor (lb_loss slot / padding);
    // the main tensor region is zeroed inside router_kernel.
    if (out_size > TOKENS * DD) {
        cudaMemsetAsync(out + (size_t)TOKENS * DD, 0,
                        sizeof(float) * (size_t)(out_size - TOKENS * DD), 0);
    }

    moe_init_kernel<<<1, 32>>>();
    router_kernel<<<TOKENS / 16, 256>>>(x, Wr, out);
    scan_kernel<<<1, 512>>>(out, out_size);
    ffn1_kernel<<<dim3(FF / 8, EE), 256>>>(x, W1, b1);
    ffn2_kernel<<<dim3(DD / 8, EE), 256>>>(W2, b2, out);
}

// round 13
// speedup vs baseline: 1.0512x; 1.0512x over previous
#include <cuda_runtime.h>
#include <math.h>

// ---------------------------------------------------------------------------
// SwitchMoE: B=8,T=2048,D=1024,F=4096,E=16 -> tokens=16384
// capacity=1280, K=13. Only per-expert rank%1280==0 tokens are processed
// (~1/expert). nonzero(size=K, fill_value=0) artifact: token 0's expert
// output is scaled by (K - kept_e0 + 1). Kept tokens are unique -> plain
// stores into zeroed output (zeroing fused into router).
// ---------------------------------------------------------------------------

#define TOKENS 16384
#define DD     1024
#define EE     16
#define FF     4096
#define CAP    1280
#define KK     13
#define NW     (EE * KK)          /* 208 */
#define RBLK   1024               /* router blocks (16 tokens each) */

// ---- device scratch (no allocations allowed) ------------------------------
__device__ int   g_top1[TOKENS];
__device__ float g_top1p[TOKENS];
__device__ float g_part[RBLK * EE];      // per-block softmax partial sums
__device__ int   g_wtok[NW];
__device__ float g_wscale[NW];
__device__ float g_h[(size_t)NW * FF];   // ~3.4 MB

// ---------------------------------------------------------------------------
// Router: 16 tokens/block (8 warps x 2 tokens). Wr staged in shared (two
// 8-expert passes, 32KB); x rows in registers so each LDS.128 feeds 8 FMAs.
// No atomics: per-block prob sums reduced through shared -> g_part.
// Also zeroes this block's 16 output rows.
// ---------------------------------------------------------------------------
__global__ void __launch_bounds__(256)
router_kernel(const float* __restrict__ x,
              const float* __restrict__ Wr,
              float* __restrict__ out) {
    __shared__ float sWr[8 * DD];        // 32 KB
    __shared__ float sProbs[16][EE + 1]; // padded vs bank conflicts

    const int tid  = threadIdx.x;
    const int warp = tid >> 5;
    const int lane = tid & 31;
    const int tBase = blockIdx.x * 16;
    const int t0 = tBase + warp * 2;

    // zero the 16 output rows this block owns
    {
        float4* o = (float4*)(out + (size_t)tBase * DD);
        const float4 z = make_float4(0.f, 0.f, 0.f, 0.f);
        #pragma unroll
        for (int j = tid; j < 16 * DD / 4; j += 256) o[j] = z;
    }

    // x rows for the warp's two tokens -> registers
    float4 xa[8], xb[8];
    {
        const float4* X0 = (const float4*)(x + (size_t)t0 * DD);
        const float4* X1 = (const float4*)(x + (size_t)(t0 + 1) * DD);
        #pragma unroll
        for (int i = 0; i < 8; i++) { xa[i] = X0[lane + i * 32]; xb[i] = X1[lane + i * 32]; }
    }

    float acc0[EE], acc1[EE];
    #pragma unroll
    for (int e = 0; e < EE; e++) { acc0[e] = 0.f; acc1[e] = 0.f; }

    #pragma unroll
    for (int pass = 0; pass < 2; pass++) {
        __syncthreads();
        {
            const float4* wsrc = (const float4*)(Wr + (size_t)pass * 8 * DD);
            float4* sdst = (float4*)sWr;
            #pragma unroll
            for (int j = tid; j < 8 * DD / 4; j += 256) sdst[j] = wsrc[j];
        }
        __syncthreads();
        #pragma unroll
        for (int e8 = 0; e8 < 8; e8++) {
            const float4* w = (const float4*)(sWr + e8 * DD);
            float s0 = 0.f, s1 = 0.f;
            #pragma unroll
            for (int i = 0; i < 8; i++) {
                float4 wv = w[lane + i * 32];
                s0 += xa[i].x * wv.x + xa[i].y * wv.y + xa[i].z * wv.z + xa[i].w * wv.w;
                s1 += xb[i].x * wv.x + xb[i].y * wv.y + xb[i].z * wv.z + xb[i].w * wv.w;
            }
            acc0[pass * 8 + e8] += s0;
            acc1[pass * 8 + e8] += s1;
        }
    }

    // reduce partial logits across the warp
    #pragma unroll
    for (int off = 16; off; off >>= 1) {
        #pragma unroll
        for (int e = 0; e < EE; e++) {
            acc0[e] += __shfl_xor_sync(0xffffffffu, acc0[e], off);
            acc1[e] += __shfl_xor_sync(0xffffffffu, acc1[e], off);
        }
    }

    if (lane < 2) {
        const float* a = lane ? acc1 : acc0;
        const int t = t0 + lane;
        float m = a[0]; int am = 0;
        #pragma unroll
        for (int e = 1; e < EE; e++) if (a[e] > m) { m = a[e]; am = e; }
        float p[EE];
        float s = 0.f;
        #pragma unroll
        for (int e = 0; e < EE; e++) { p[e] = expf(a[e] - m); s += p[e]; }
        const float inv = 1.0f / s;
        g_top1[t]  = am;
        g_top1p[t] = p[am] * inv;
        #pragma unroll
        for (int e = 0; e < EE; e++) sProbs[warp * 2 + lane][e] = p[e] * inv;
    }
    __syncthreads();
    if (tid < EE) {
        float s = 0.f;
        #pragma unroll
        for (int j = 0; j < 16; j++) s += sProbs[j][tid];
        g_part[blockIdx.x * EE + tid] = s;
    }
}

// ---------------------------------------------------------------------------
// Scan: 1 block, 16 warps; warp e walks tokens in order via ballot (exact
// in-order ranks), records rank%CAP==0 tokens, applies the token-0 fill
// multiplier, reduces g_part -> lb_loss.
// ---------------------------------------------------------------------------
__global__ void __launch_bounds__(512)
scan_kernel(float* __restrict__ out, int out_size) {
    const int tid  = threadIdx.x;
    const int e    = tid >> 5;
    const int lane = tid & 31;
    __shared__ int   sCnt[EE];
    __shared__ float sPsum[EE];

    if (tid < EE) sPsum[tid] = 0.f;
    if (lane < KK) { g_wtok[e * KK + lane] = -1; g_wscale[e * KK + lane] = 0.f; }

    int cnt = 0;
    #pragma unroll 16
    for (int base = 0; base < TOKENS; base += 32) {
        const int t = base + lane;
        const bool m = (g_top1[t] == e);
        const unsigned msk = __ballot_sync(0xffffffffu, m);
        if (m) {
            const int r = cnt + __popc(msk & ((1u << lane) - 1u));
            if (r % CAP == 0) {
                const int slot = r / CAP;
                g_wtok[e * KK + slot]   = t;
                g_wscale[e * KK + slot] = g_top1p[t];
            }
        }
        cnt += __popc(msk);
    }
    if (lane == 0) sCnt[e] = cnt;

    // reduce g_part[1024][16]: thread tid covers expert tid&15, chunks tid>>4
    __syncthreads();
    {
        const int ee = tid & 15;
        float s = 0.f;
        for (int i = tid >> 4; i < RBLK; i += 32)
            s += g_part[i * EE + ee];
        atomicAdd(&sPsum[ee], s);
    }
    __syncthreads();

    if (tid == 0) {
        const int e0 = g_top1[0];
        const int c0 = sCnt[e0];
        const int kept0 = (c0 - 1) / CAP + 1;
        g_wscale[e0 * KK + 0] *= (float)(KK - kept0 + 1);

        if (out_size > TOKENS * DD) {
            float lb = 0.f;
            for (int j = 0; j < EE; j++)
                lb += ((float)sCnt[j] / (float)TOKENS) * (sPsum[j] / (float)TOKENS);
            out[(size_t)TOKENS * DD] = lb * (float)EE * 0.01f;
        }
    }
}

// ---------------------------------------------------------------------------
// FFN1: h = gelu(W1[e] @ x[t] + b1[e]); warp handles rows f and f+F/2
// (16 outstanding LDG.128 per lane). grid(F/16, E).
// ---------------------------------------------------------------------------
__global__ void __launch_bounds__(256)
ffn1_kernel(const float* __restrict__ x,
            const float* __restrict__ W1,
            const float* __restrict__ b1) {
    __shared__ float sx[DD];   // 4 KB
    const int tid  = threadIdx.x;
    const int warp = tid >> 5;
    const int lane = tid & 31;
    const int e    = blockIdx.y;
    const int f0   = blockIdx.x * 8 + warp;
    const int f1   = f0 + FF / 2;

    for (int k = 0; k < KK; k++) {
        const int t = g_wtok[e * KK + k];
        if (t < 0) break;
        __syncthreads();
        ((float4*)sx)[tid] = ((const float4*)(x + (size_t)t * DD))[tid];
        __syncthreads();

        const float4* w0 = (const float4*)(W1 + ((size_t)e * FF + f0) * DD);
        const float4* w1 = (const float4*)(W1 + ((size_t)e * FF + f1) * DD);
        const float4* xv = (const float4*)sx;
        float s0 = 0.f, s1 = 0.f;
        #pragma unroll
        for (int i = 0; i < 8; i++) {
            const float4 a = w0[lane + i * 32];
            const float4 b = w1[lane + i * 32];
            const float4 xx = xv[lane + i * 32];
            s0 += a.x * xx.x + a.y * xx.y + a.z * xx.z + a.w * xx.w;
            s1 += b.x * xx.x + b.y * xx.y + b.z * xx.z + b.w * xx.w;
        }
        #pragma unroll
        for (int off = 16; off; off >>= 1) {
            s0 += __shfl_xor_sync(0xffffffffu, s0, off);
            s1 += __shfl_xor_sync(0xffffffffu, s1, off);
        }
        if (lane == 0) {
            float* hrow = g_h + ((size_t)(e * KK + k)) * FF;
            const float v0 = s0 + b1[e * FF + f0];
            const float v1 = s1 + b1[e * FF + f1];
            hrow[f0] = 0.5f * v0 * (1.0f + erff(v0 * 0.70710678118654752f));
            hrow[f1] = 0.5f * v1 * (1.0f + erff(v1 * 0.70710678118654752f));
        }
    }
}

// ---------------------------------------------------------------------------
// FFN2: out[t] = (W2[e] @ h + b2[e]) * scale; warp handles rows d and d+D/2.
// Kept tokens unique across experts -> plain store. grid(D/16, E).
// ---------------------------------------------------------------------------
__global__ void __launch_bounds__(256)
ffn2_kernel(const float* __restrict__ W2,
            const float* __restrict__ b2,
            float* __restrict__ out) {
    __shared__ float sh[FF];   // 16 KB
    const int tid  = threadIdx.x;
    const int warp = tid >> 5;
    const int lane = tid & 31;
    const int e    = blockIdx.y;
    const int d0   = blockIdx.x * 8 + warp;
    const int d1   = d0 + DD / 2;

    for (int k = 0; k < KK; k++) {
        const int t = g_wtok[e * KK + k];
        if (t < 0) break;
        const float scale = g_wscale[e * KK + k];
        __syncthreads();
        {
            const float4* hs = (const float4*)(g_h + ((size_t)(e * KK + k)) * FF);
            float4* sd = (float4*)sh;
            #pragma unroll
            for (int j = tid; j < FF / 4; j += 256) sd[j] = hs[j];
        }
        __syncthreads();

        const float4* w0 = (const float4*)(W2 + ((size_t)e * DD + d0) * FF);
        const float4* w1 = (const float4*)(W2 + ((size_t)e * DD + d1) * FF);
        const float4* hv = (const float4*)sh;
        float s0 = 0.f, s1 = 0.f;
        #pragma unroll 8
        for (int i = 0; i < 32; i++) {
            const float4 a = w0[lane + i * 32];
            const float4 b = w1[lane + i * 32];
            const float4 hh = hv[lane + i * 32];
            s0 += a.x * hh.x + a.y * hh.y + a.z * hh.z + a.w * hh.w;
            s1 += b.x * hh.x + b.y * hh.y + b.z * hh.z + b.w * hh.w;
        }
        #pragma unroll
        for (int off = 16; off; off >>= 1) {
            s0 += __shfl_xor_sync(0xffffffffu, s0, off);
            s1 += __shfl_xor_sync(0xffffffffu, s1, off);
        }
        if (lane == 0) {
            out[(size_t)t * DD + d0] = (s0 + b2[e * DD + d0]) * scale;
            out[(size_t)t * DD + d1] = (s1 + b2[e * DD + d1]) * scale;
        }
    }
}

// ---------------------------------------------------------------------------
extern "C" void kernel_launch(void* const* d_in, const int* in_sizes, int n_in,
                              void* d_out, int out_size) {
    const float* x  = (const float*)d_in[0];
    const float* Wr = (const float*)d_in[1];
    const float* W1 = (const float*)d_in[2];
    const float* b1 = (const float*)d_in[3];
    const float* W2 = (const float*)d_in[4];
    const float* b2 = (const float*)d_in[5];
    float* out = (float*)d_out;
    (void)in_sizes; (void)n_in;

    if (out_size > TOKENS * DD) {
        cudaMemsetAsync(out + (size_t)TOKENS * DD, 0,
                        sizeof(float) * (size_t)(out_size - TOKENS * DD), 0);
    }

    router_kernel<<<RBLK, 256>>>(x, Wr, out);
    scan_kernel<<<1, 512>>>(out, out_size);
    ffn1_kernel<<<dim3(FF / 16, EE), 256>>>(x, W1, b1);
    ffn2_kernel<<<dim3(DD / 16, EE), 256>>>(W2, b2, out);
}

// round 14
// speedup vs baseline: 1.0741x; 1.0219x over previous
#include <cuda_runtime.h>
#include <math.h>

// ---------------------------------------------------------------------------
// SwitchMoE: B=8,T=2048,D=1024,F=4096,E=16 -> tokens=16384
// capacity=1280, K=13. Only per-expert rank%1280==0 tokens are processed
// (~1/expert). nonzero(size=K, fill_value=0) artifact: token 0's expert
// output is scaled by (K - kept_e0 + 1). Kept tokens are unique -> plain
// stores into zeroed output (zeroing fused into router).
// ---------------------------------------------------------------------------

#define TOKENS 16384
#define DD     1024
#define EE     16
#define FF     4096
#define CAP    1280
#define KK     13
#define NW     (EE * KK)          /* 208 */
#define RBLK   1024               /* router blocks (16 tokens each) */

// ---- device scratch (no allocations allowed) ------------------------------
__device__ int   g_top1[TOKENS];
__device__ float g_top1p[TOKENS];
__device__ float g_part[RBLK * EE];      // per-block softmax partial sums
__device__ int   g_wtok[NW];
__device__ float g_wscale[NW];
__device__ float g_h[(size_t)NW * FF];   // ~3.4 MB

// ---------------------------------------------------------------------------
// Router: 16 tokens/block (8 warps x 2 tokens). Wr staged in shared (two
// 8-expert passes, 32KB); x rows in registers so each LDS.128 feeds 8 FMAs.
// No atomics: per-block prob sums reduced through shared -> g_part.
// Also zeroes this block's 16 output rows.
// ---------------------------------------------------------------------------
__global__ void __launch_bounds__(256)
router_kernel(const float* __restrict__ x,
              const float* __restrict__ Wr,
              float* __restrict__ out) {
    __shared__ float sWr[8 * DD];        // 32 KB
    __shared__ float sProbs[16][EE + 1]; // padded vs bank conflicts

    const int tid  = threadIdx.x;
    const int warp = tid >> 5;
    const int lane = tid & 31;
    const int tBase = blockIdx.x * 16;
    const int t0 = tBase + warp * 2;

    // zero the 16 output rows this block owns
    {
        float4* o = (float4*)(out + (size_t)tBase * DD);
        const float4 z = make_float4(0.f, 0.f, 0.f, 0.f);
        #pragma unroll
        for (int j = tid; j < 16 * DD / 4; j += 256) o[j] = z;
    }

    // x rows for the warp's two tokens -> registers
    float4 xa[8], xb[8];
    {
        const float4* X0 = (const float4*)(x + (size_t)t0 * DD);
        const float4* X1 = (const float4*)(x + (size_t)(t0 + 1) * DD);
        #pragma unroll
        for (int i = 0; i < 8; i++) { xa[i] = X0[lane + i * 32]; xb[i] = X1[lane + i * 32]; }
    }

    float acc0[EE], acc1[EE];
    #pragma unroll
    for (int e = 0; e < EE; e++) { acc0[e] = 0.f; acc1[e] = 0.f; }

    #pragma unroll
    for (int pass = 0; pass < 2; pass++) {
        __syncthreads();
        {
            const float4* wsrc = (const float4*)(Wr + (size_t)pass * 8 * DD);
            float4* sdst = (float4*)sWr;
            #pragma unroll
            for (int j = tid; j < 8 * DD / 4; j += 256) sdst[j] = wsrc[j];
        }
        __syncthreads();
        #pragma unroll
        for (int e8 = 0; e8 < 8; e8++) {
            const float4* w = (const float4*)(sWr + e8 * DD);
            float s0 = 0.f, s1 = 0.f;
            #pragma unroll
            for (int i = 0; i < 8; i++) {
                float4 wv = w[lane + i * 32];
                s0 += xa[i].x * wv.x + xa[i].y * wv.y + xa[i].z * wv.z + xa[i].w * wv.w;
                s1 += xb[i].x * wv.x + xb[i].y * wv.y + xb[i].z * wv.z + xb[i].w * wv.w;
            }
            acc0[pass * 8 + e8] += s0;
            acc1[pass * 8 + e8] += s1;
        }
    }

    // reduce partial logits across the warp
    #pragma unroll
    for (int off = 16; off; off >>= 1) {
        #pragma unroll
        for (int e = 0; e < EE; e++) {
            acc0[e] += __shfl_xor_sync(0xffffffffu, acc0[e], off);
            acc1[e] += __shfl_xor_sync(0xffffffffu, acc1[e], off);
        }
    }

    if (lane < 2) {
        const float* a = lane ? acc1 : acc0;
        const int t = t0 + lane;
        float m = a[0]; int am = 0;
        #pragma unroll
        for (int e = 1; e < EE; e++) if (a[e] > m) { m = a[e]; am = e; }
        float p[EE];
        float s = 0.f;
        #pragma unroll
        for (int e = 0; e < EE; e++) { p[e] = expf(a[e] - m); s += p[e]; }
        const float inv = 1.0f / s;
        g_top1[t]  = am;
        g_top1p[t] = p[am] * inv;
        #pragma unroll
        for (int e = 0; e < EE; e++) sProbs[warp * 2 + lane][e] = p[e] * inv;
    }
    __syncthreads();
    if (tid < EE) {
        float s = 0.f;
        #pragma unroll
        for (int j = 0; j < 16; j++) s += sProbs[j][tid];
        g_part[blockIdx.x * EE + tid] = s;
    }
}

// ---------------------------------------------------------------------------
// Scan: 1 block, 16 warps; warp e walks tokens in order via ballot (exact
// in-order ranks), records rank%CAP==0 tokens, applies the token-0 fill
// multiplier, reduces g_part -> lb_loss.
// ---------------------------------------------------------------------------
__global__ void __launch_bounds__(512)
scan_kernel(float* __restrict__ out, int out_size) {
    const int tid  = threadIdx.x;
    const int e    = tid >> 5;
    const int lane = tid & 31;
    __shared__ int   sCnt[EE];
    __shared__ float sPsum[EE];

    if (tid < EE) sPsum[tid] = 0.f;
    if (lane < KK) { g_wtok[e * KK + lane] = -1; g_wscale[e * KK + lane] = 0.f; }

    int cnt = 0;
    #pragma unroll 16
    for (int base = 0; base < TOKENS; base += 32) {
        const int t = base + lane;
        const bool m = (g_top1[t] == e);
        const unsigned msk = __ballot_sync(0xffffffffu, m);
        if (m) {
            const int r = cnt + __popc(msk & ((1u << lane) - 1u));
            if (r % CAP == 0) {
                const int slot = r / CAP;
                g_wtok[e * KK + slot]   = t;
                g_wscale[e * KK + slot] = g_top1p[t];
            }
        }
        cnt += __popc(msk);
    }
    if (lane == 0) sCnt[e] = cnt;

    // reduce g_part[1024][16]: thread tid covers expert tid&15, chunks tid>>4
    __syncthreads();
    {
        const int ee = tid & 15;
        float s = 0.f;
        for (int i = tid >> 4; i < RBLK; i += 32)
            s += g_part[i * EE + ee];
        atomicAdd(&sPsum[ee], s);
    }
    __syncthreads();

    if (tid == 0) {
        const int e0 = g_top1[0];
        const int c0 = sCnt[e0];
        const int kept0 = (c0 - 1) / CAP + 1;
        g_wscale[e0 * KK + 0] *= (float)(KK - kept0 + 1);

        if (out_size > TOKENS * DD) {
            float lb = 0.f;
            for (int j = 0; j < EE; j++)
                lb += ((float)sCnt[j] / (float)TOKENS) * (sPsum[j] / (float)TOKENS);
            out[(size_t)TOKENS * DD] = lb * (float)EE * 0.01f;
        }
    }
}

// ---------------------------------------------------------------------------
// FFN1: h = gelu(W1[e] @ x[t] + b1[e]); warp handles rows f and f+F/2
// (16 outstanding LDG.128 per lane). grid(F/16, E).
// ---------------------------------------------------------------------------
__global__ void __launch_bounds__(256)
ffn1_kernel(const float* __restrict__ x,
            const float* __restrict__ W1,
            const float* __restrict__ b1) {
    __shared__ float sx[DD];   // 4 KB
    const int tid  = threadIdx.x;
    const int warp = tid >> 5;
    const int lane = tid & 31;
    const int e    = blockIdx.y;
    const int f0   = blockIdx.x * 8 + warp;
    const int f1   = f0 + FF / 2;

    for (int k = 0; k < KK; k++) {
        const int t = g_wtok[e * KK + k];
        if (t < 0) break;
        __syncthreads();
        ((float4*)sx)[tid] = ((const float4*)(x + (size_t)t * DD))[tid];
        __syncthreads();

        const float4* w0 = (const float4*)(W1 + ((size_t)e * FF + f0) * DD);
        const float4* w1 = (const float4*)(W1 + ((size_t)e * FF + f1) * DD);
        const float4* xv = (const float4*)sx;
        float s0 = 0.f, s1 = 0.f;
        #pragma unroll
        for (int i = 0; i < 8; i++) {
            const float4 a = w0[lane + i * 32];
            const float4 b = w1[lane + i * 32];
            const float4 xx = xv[lane + i * 32];
            s0 += a.x * xx.x + a.y * xx.y + a.z * xx.z + a.w * xx.w;
            s1 += b.x * xx.x + b.y * xx.y + b.z * xx.z + b.w * xx.w;
        }
        #pragma unroll
        for (int off = 16; off; off >>= 1) {
            s0 += __shfl_xor_sync(0xffffffffu, s0, off);
            s1 += __shfl_xor_sync(0xffffffffu, s1, off);
        }
        if (lane == 0) {
            float* hrow = g_h + ((size_t)(e * KK + k)) * FF;
            const float v0 = s0 + b1[e * FF + f0];
            const float v1 = s1 + b1[e * FF + f1];
            hrow[f0] = 0.5f * v0 * (1.0f + erff(v0 * 0.70710678118654752f));
            hrow[f1] = 0.5f * v1 * (1.0f + erff(v1 * 0.70710678118654752f));
        }
    }
}

// ---------------------------------------------------------------------------
// FFN2: out[t] = (W2[e] @ h + b2[e]) * scale; warp handles rows d and d+D/2.
// Kept tokens unique across experts -> plain store. grid(D/16, E).
// ---------------------------------------------------------------------------
__global__ void __launch_bounds__(256)
ffn2_kernel(const float* __restrict__ W2,
            const float* __restrict__ b2,
            float* __restrict__ out) {
    __shared__ float sh[FF];   // 16 KB
    const int tid  = threadIdx.x;
    const int warp = tid >> 5;
    const int lane = tid & 31;
    const int e    = blockIdx.y;
    const int d0   = blockIdx.x * 8 + warp;
    const int d1   = d0 + DD / 2;

    for (int k = 0; k < KK; k++) {
        const int t = g_wtok[e * KK + k];
        if (t < 0) break;
        const float scale = g_wscale[e * KK + k];
        __syncthreads();
        {
            const float4* hs = (const float4*)(g_h + ((size_t)(e * KK + k)) * FF);
            float4* sd = (float4*)sh;
            #pragma unroll
            for (int j = tid; j < FF / 4; j += 256) sd[j] = hs[j];
        }
        __syncthreads();

        const float4* w0 = (const float4*)(W2 + ((size_t)e * DD + d0) * FF);
        const float4* w1 = (const float4*)(W2 + ((size_t)e * DD + d1) * FF);
        const float4* hv = (const float4*)sh;
        float s0 = 0.f, s1 = 0.f;
        #pragma unroll 8
        for (int i = 0; i < 32; i++) {
            const float4 a = w0[lane + i * 32];
            const float4 b = w1[lane + i * 32];
            const float4 hh = hv[lane + i * 32];
            s0 += a.x * hh.x + a.y * hh.y + a.z * hh.z + a.w * hh.w;
            s1 += b.x * hh.x + b.y * hh.y + b.z * hh.z + b.w * hh.w;
        }
        #pragma unroll
        for (int off = 16; off; off >>= 1) {
            s0 += __shfl_xor_sync(0xffffffffu, s0, off);
            s1 += __shfl_xor_sync(0xffffffffu, s1, off);
        }
        if (lane == 0) {
            out[(size_t)t * DD + d0] = (s0 + b2[e * DD + d0]) * scale;
            out[(size_t)t * DD + d1] = (s1 + b2[e * DD + d1]) * scale;
        }
    }
}

// ---------------------------------------------------------------------------
extern "C" void kernel_launch(void* const* d_in, const int* in_sizes, int n_in,
                              void* d_out, int out_size) {
    const float* x  = (const float*)d_in[0];
    const float* Wr = (const float*)d_in[1];
    const float* W1 = (const float*)d_in[2];
    const float* b1 = (const float*)d_in[3];
    const float* W2 = (const float*)d_in[4];
    const float* b2 = (const float*)d_in[5];
    float* out = (float*)d_out;
    (void)in_sizes; (void)n_in;

    if (out_size > TOKENS * DD) {
        cudaMemsetAsync(out + (size_t)TOKENS * DD, 0,
                        sizeof(float) * (size_t)(out_size - TOKENS * DD), 0);
    }

    router_kernel<<<RBLK, 256>>>(x, Wr, out);
    scan_kernel<<<1, 512>>>(out, out_size);
    ffn1_kernel<<<dim3(FF / 16, EE), 256>>>(x, W1, b1);
    ffn2_kernel<<<dim3(DD / 16, EE), 256>>>(W2, b2, out);
}